// round 9
// baseline (speedup 1.0000x reference)
#include <cuda_runtime.h>
#include <cuda_fp16.h>
#include <cstdint>

#define NN 100000
#define NE 6400000
#define DIN 128
#define HID 16
#define TOT (NN * HID)
#define NB1 391            // ceil(NN/256)

// ---------------- scratch (static device globals; no allocation) ----------------
__device__ __align__(16) __half g_h1[TOT];   // fp16: dinv[n] * (xn @ W1)
__device__ __align__(16) __half g_t[TOT];    // fp16: dinv[n] * (dropout(relu(conv1)) @ W2)
__device__ __align__(16) float  g_a1[TOT];   // scratch: raw xn@W1 (fp32), then conv1 gather sums
__device__ __align__(16) float  g_a2[TOT];   // conv2 raw gather sums (fp32)
__device__ float g_dinv[NN];
__device__ int   g_cnt[NN];                  // in-degree (excl self-loop); re-zeroed each replay
__device__ int   g_off[NN];                  // CSR row start
__device__ int   g_cur[NN];                  // fill cursor -> row end after fill
__device__ int   g_bsum[512];                // block sums for scan
__device__ int   g_csrc[NE];                 // CSR: src per slot

// ---------------- JAX Threefry-2x32 (20 rounds), bit-exact ----------------
__host__ __device__ __forceinline__ void threefry2x32(
    uint32_t k0, uint32_t k1, uint32_t x0, uint32_t x1,
    uint32_t& o0, uint32_t& o1)
{
    uint32_t ks2 = k0 ^ k1 ^ 0x1BD11BDAu;
    x0 += k0; x1 += k1;
#define TF_R(r) { x0 += x1; x1 = (x1 << r) | (x1 >> (32 - r)); x1 ^= x0; }
    TF_R(13) TF_R(15) TF_R(26) TF_R(6)
    x0 += k1;  x1 += ks2 + 1u;
    TF_R(17) TF_R(29) TF_R(16) TF_R(24)
    x0 += ks2; x1 += k0 + 2u;
    TF_R(13) TF_R(15) TF_R(26) TF_R(6)
    x0 += k0;  x1 += k1 + 3u;
    TF_R(17) TF_R(29) TF_R(16) TF_R(24)
    x0 += k1;  x1 += ks2 + 4u;
    TF_R(13) TF_R(15) TF_R(26) TF_R(6)
    x0 += ks2; x1 += k0 + 5u;
#undef TF_R
    o0 = x0; o1 = x1;
}

// Partitionable-mode random_bits: counter (0, i); output = o0 ^ o1.
__device__ __forceinline__ float dropout_elem(float h, uint32_t k0, uint32_t k1, uint32_t i)
{
    uint32_t o0, o1;
    threefry2x32(k0, k1, 0u, i, o0, o1);
    uint32_t bits = o0 ^ o1;
    float u = __uint_as_float((bits >> 9) | 0x3F800000u) - 1.0f;
    return (u >= 0.3f) ? (h / 0.7f) : 0.0f;
}

// load 8 consecutive halfs (16B, one LDG.128) -> 8 floats
__device__ __forceinline__ void ld_h8(const __half* p, float* f)
{
    uint4 r = *(const uint4*)p;
    __half2 h0 = *(__half2*)&r.x, h1 = *(__half2*)&r.y,
            h2 = *(__half2*)&r.z, h3 = *(__half2*)&r.w;
    float2 f0 = __half22float2(h0), f1 = __half22float2(h1),
           f2 = __half22float2(h2), f3 = __half22float2(h3);
    f[0] = f0.x; f[1] = f0.y; f[2] = f1.x; f[3] = f1.y;
    f[4] = f2.x; f[5] = f2.y; f[6] = f3.x; f[7] = f3.y;
}

// ---------------- CSR build ----------------
__global__ void k_hist(const int4* __restrict__ dst4)
{
    unsigned i = blockIdx.x * blockDim.x + threadIdx.x;   // grid covers NE/4 exactly
    int4 d = dst4[i];
    atomicAdd(&g_cnt[d.x], 1);
    atomicAdd(&g_cnt[d.y], 1);
    atomicAdd(&g_cnt[d.z], 1);
    atomicAdd(&g_cnt[d.w], 1);
}

// block-wide exclusive scan via warp shuffles (256 threads)
__global__ void k_scan1()
{
    __shared__ int wsum[8];
    unsigned t = threadIdx.x, wid = t >> 5, lane = t & 31;
    unsigned i = blockIdx.x * 256 + t;
    int v = (i < NN) ? g_cnt[i] : 0;

    int sc = v;
#pragma unroll
    for (int d = 1; d < 32; d <<= 1) {
        int o = __shfl_up_sync(0xffffffffu, sc, d);
        if (lane >= (unsigned)d) sc += o;
    }
    if (lane == 31) wsum[wid] = sc;
    __syncthreads();
    if (wid == 0 && lane < 8) {
        int w = wsum[lane];
#pragma unroll
        for (int d = 1; d < 8; d <<= 1) {
            int o = __shfl_up_sync(0x000000ffu, w, d);
            if (lane >= (unsigned)d) w += o;
        }
        wsum[lane] = w;
    }
    __syncthreads();
    int incl = sc + (wid ? wsum[wid - 1] : 0);
    if (i < NN) g_off[i] = incl - v;             // exclusive
    if (t == 255) g_bsum[blockIdx.x] = incl;     // block total
}

// single-block exclusive scan over NB1 block sums (512 threads)
__global__ void k_scan2()
{
    __shared__ int wsum[16];
    unsigned t = threadIdx.x, wid = t >> 5, lane = t & 31;
    int v = (t < NB1) ? g_bsum[t] : 0;

    int sc = v;
#pragma unroll
    for (int d = 1; d < 32; d <<= 1) {
        int o = __shfl_up_sync(0xffffffffu, sc, d);
        if (lane >= (unsigned)d) sc += o;
    }
    if (lane == 31) wsum[wid] = sc;
    __syncthreads();
    if (wid == 0 && lane < 16) {
        int w = wsum[lane];
#pragma unroll
        for (int d = 1; d < 16; d <<= 1) {
            int o = __shfl_up_sync(0x0000ffffu, w, d);
            if (lane >= (unsigned)d) w += o;
        }
        wsum[lane] = w;
    }
    __syncthreads();
    int incl = sc + (wid ? wsum[wid - 1] : 0);
    g_bsum[t] = incl - v;                        // exclusive block offsets
}

// finalize offsets/cursors/dinv, then re-zero cnt for the next replay
__global__ void k_scan3()
{
    unsigned i = blockIdx.x * blockDim.x + threadIdx.x;
    if (i < NN) {
        int o = g_off[i] + g_bsum[i >> 8];
        g_off[i] = o;
        g_cur[i] = o;
        g_dinv[i] = rsqrtf((float)(g_cnt[i] + 1));   // +1 self-loop
        g_cnt[i] = 0;                                // replay invariant
    }
}

__global__ void k_fill(const int4* __restrict__ src4, const int4* __restrict__ dst4)
{
    unsigned i = blockIdx.x * blockDim.x + threadIdx.x;   // grid covers NE/4 exactly
    int4 s = src4[i];
    int4 d = dst4[i];
    g_csrc[atomicAdd(&g_cur[d.x], 1)] = s.x;
    g_csrc[atomicAdd(&g_cur[d.y], 1)] = s.y;
    g_csrc[atomicAdd(&g_cur[d.z], 1)] = s.z;
    g_csrc[atomicAdd(&g_cur[d.w], 1)] = s.w;
}

// ---------------- LayerNorm + GEMM1 (warp per node), RAW fp32 out -> g_a1 ----------------
// Independent of the CSR build (no dinv) so it can run on a parallel stream.
__global__ __launch_bounds__(256, 2) void k_ln_gemm(
    const float* __restrict__ x,
    const float* __restrict__ gamma, const float* __restrict__ beta,
    const float* __restrict__ W1)
{
    unsigned l = threadIdx.x & 31;
    unsigned warp = blockIdx.x * (blockDim.x >> 5) + (threadIdx.x >> 5);
    unsigned nwarps = gridDim.x * (blockDim.x >> 5);

    float4 g4 = *(const float4*)(gamma + l * 4);
    float4 b4 = *(const float4*)(beta + l * 4);
    float4 w[16];
#pragma unroll
    for (int c = 0; c < 4; ++c)
#pragma unroll
        for (int q = 0; q < 4; ++q)
            w[c * 4 + q] = *(const float4*)(W1 + (size_t)(l * 4 + c) * 16 + q * 4);

    unsigned n = warp;
    float4 xv = make_float4(0.f, 0.f, 0.f, 0.f);
    if (n < NN) xv = *(const float4*)(x + (size_t)n * DIN + l * 4);

    while (n < NN) {
        unsigned n2 = n + nwarps;                 // prefetch next node
        float4 xv2 = make_float4(0.f, 0.f, 0.f, 0.f);
        if (n2 < NN) xv2 = *(const float4*)(x + (size_t)n2 * DIN + l * 4);

        float s  = xv.x + xv.y + xv.z + xv.w;
        float ss = xv.x * xv.x + xv.y * xv.y + xv.z * xv.z + xv.w * xv.w;
#pragma unroll
        for (int d = 16; d >= 1; d >>= 1) {
            s  += __shfl_xor_sync(0xffffffffu, s,  d);
            ss += __shfl_xor_sync(0xffffffffu, ss, d);
        }
        float mu  = s * (1.0f / 128.0f);
        float var = ss * (1.0f / 128.0f) - mu * mu;
        float rs  = rsqrtf(var + 1e-5f);

        float xn[4];
        xn[0] = (xv.x - mu) * rs * g4.x + b4.x;
        xn[1] = (xv.y - mu) * rs * g4.y + b4.y;
        xn[2] = (xv.z - mu) * rs * g4.z + b4.z;
        xn[3] = (xv.w - mu) * rs * g4.w + b4.w;

        float p[16];
#pragma unroll
        for (int j = 0; j < 16; ++j) p[j] = 0.0f;
#pragma unroll
        for (int c = 0; c < 4; ++c) {
#pragma unroll
            for (int q = 0; q < 4; ++q) {
                p[q * 4 + 0] = fmaf(xn[c], w[c * 4 + q].x, p[q * 4 + 0]);
                p[q * 4 + 1] = fmaf(xn[c], w[c * 4 + q].y, p[q * 4 + 1]);
                p[q * 4 + 2] = fmaf(xn[c], w[c * 4 + q].z, p[q * 4 + 2]);
                p[q * 4 + 3] = fmaf(xn[c], w[c * 4 + q].w, p[q * 4 + 3]);
            }
        }
        {
            bool hi;
#define RED_STEP(D, M)                                                        \
            hi = (l & D) != 0;                                                \
            _Pragma("unroll")                                                 \
            for (int i = 0; i < M; ++i) {                                     \
                float send  = hi ? p[i] : p[i + M];                           \
                float other = __shfl_xor_sync(0xffffffffu, send, D);          \
                float keep  = hi ? p[i + M] : p[i];                           \
                p[i] = keep + other;                                          \
            }
            RED_STEP(16, 8) RED_STEP(8, 4) RED_STEP(4, 2) RED_STEP(2, 1)
#undef RED_STEP
            p[0] += __shfl_xor_sync(0xffffffffu, p[0], 1);
        }
        if (!(l & 1)) g_a1[(size_t)n * 16 + (l >> 1)] = p[0];   // raw fp32

        n = n2; xv = xv2;
    }
}

// ---------------- scale raw y by dinv -> fp16 h1 (single rounding) ----------------
__global__ void k_scale()
{
    unsigned i = blockIdx.x * 256 + threadIdx.x;   // 800000 exactly -> 3125 blocks
    unsigned n = i >> 3;                           // 8 half2 per node
    float2 f = ((const float2*)g_a1)[i];
    float di = g_dinv[n];
    ((__half2*)g_h1)[i] = __floats2half2_rn(f.x * di, f.y * di);
}

// ---------------- CSR gather (fp16 h): warp per dst node, 2 lanes/edge, 2x unroll ----------------
// pass=0: h=g_h1 acc=g_a1 ; pass=1: h=g_t acc=g_a2 (selected DEVICE-side)
__global__ __launch_bounds__(256) void k_gather(int pass)
{
    const __half* __restrict__ h = pass ? g_t : g_h1;
    float* __restrict__ acc      = pass ? g_a2 : g_a1;

    unsigned n = blockIdx.x * 8 + (threadIdx.x >> 5);   // 12500 * 8 = 100000 exactly
    unsigned l = threadIdx.x & 31;
    unsigned g = l >> 1, c = l & 1;                     // 16 edge-groups, 2 lanes each
    int end = g_cur[n];
    int e = g_off[n] + (int)g;

    float a[8], b[8];
#pragma unroll
    for (int i = 0; i < 8; ++i) { a[i] = 0.f; b[i] = 0.f; }

    for (; e + 16 < end; e += 32) {                     // 32 edges in flight per warp
        int s0 = __ldg(&g_csrc[e]);
        int s1 = __ldg(&g_csrc[e + 16]);
        float f0[8], f1[8];
        ld_h8(h + (size_t)s0 * 16 + c * 8, f0);
        ld_h8(h + (size_t)s1 * 16 + c * 8, f1);
#pragma unroll
        for (int i = 0; i < 8; ++i) { a[i] += f0[i]; b[i] += f1[i]; }
    }
    if (e < end) {                                      // at most one tail slot
        int s = __ldg(&g_csrc[e]);
        float f0[8];
        ld_h8(h + (size_t)s * 16 + c * 8, f0);
#pragma unroll
        for (int i = 0; i < 8; ++i) a[i] += f0[i];
    }
#pragma unroll
    for (int i = 0; i < 8; ++i) a[i] += b[i];

#pragma unroll
    for (int d = 2; d < 32; d <<= 1)
#pragma unroll
        for (int i = 0; i < 8; ++i)
            a[i] += __shfl_xor_sync(0xffffffffu, a[i], d);

    if (l < 2) {
        float f0[8];
        ld_h8(h + (size_t)n * 16 + c * 8, f0);          // self-loop
        float4 o0, o1;
        o0.x = a[0] + f0[0]; o0.y = a[1] + f0[1]; o0.z = a[2] + f0[2]; o0.w = a[3] + f0[3];
        o1.x = a[4] + f0[4]; o1.y = a[5] + f0[5]; o1.z = a[6] + f0[6]; o1.w = a[7] + f0[7];
        *(float4*)(acc + (size_t)n * 16 + c * 8)     = o0;
        *(float4*)(acc + (size_t)n * 16 + c * 8 + 4) = o1;
    }
}

// ---------------- post conv1: dinv*sum + b1, relu, dropout(dk1), @W2, prescale, fp16 out ----------------
__global__ void k_post1(const float* __restrict__ b1, const float* __restrict__ W2,
                        uint32_t k0, uint32_t k1)
{
    __shared__ float w2s[256];
    unsigned tid = threadIdx.x;
    w2s[tid] = W2[tid];
    __syncthreads();

    unsigned idx = blockIdx.x * blockDim.x + tid;   // grid covers TOT exactly
    unsigned n = idx >> 4, j = idx & 15;
    float di = g_dinv[n];
    float v = fmaxf(fmaf(di, g_a1[idx], b1[j]), 0.0f);
    v = dropout_elem(v, k0, k1, idx);

    float acc = 0.0f;
#pragma unroll
    for (int jj = 0; jj < 16; ++jj) {
        float hv = __shfl_sync(0xffffffffu, v, jj, 16);
        acc = fmaf(hv, w2s[jj * 16 + j], acc);
    }
    acc *= di;
    float acc2 = __shfl_down_sync(0xffffffffu, acc, 1);
    if (!(j & 1))
        *(__half2*)(g_t + (size_t)n * 16 + j) = __floats2half2_rn(acc, acc2);
}

// ---------------- final: dinv*sum + b2, relu, dropout(dk2) -> out ----------------
__global__ void k_final(float* __restrict__ out, const float* __restrict__ b2,
                        uint32_t k0, uint32_t k1)
{
    unsigned idx = blockIdx.x * blockDim.x + threadIdx.x;   // covers TOT exactly
    unsigned n = idx >> 4, j = idx & 15;
    float v = fmaxf(fmaf(g_dinv[n], g_a2[idx], b2[j]), 0.0f);
    out[idx] = dropout_elem(v, k0, k1, idx);
}

// ---------------- launch ----------------
extern "C" void kernel_launch(void* const* d_in, const int* in_sizes, int n_in,
                              void* d_out, int out_size)
{
    const float* x     = (const float*)d_in[0];
    const int*   ei    = (const int*)d_in[1];
    const float* gamma = (const float*)d_in[2];
    const float* beta  = (const float*)d_in[3];
    const float* W1    = (const float*)d_in[4];
    const float* b1    = (const float*)d_in[5];
    const float* W2    = (const float*)d_in[6];
    const float* b2    = (const float*)d_in[7];
    float* out = (float*)d_out;

    const int4* src4 = (const int4*)ei;            // edge_index[0]
    const int4* dst4 = (const int4*)(ei + NE);     // edge_index[1]

    // JAX partitionable split: dk1 = threefry(key,(0,0)), dk2 = threefry(key,(0,1))
    uint32_t A0, A1, B0, B1;
    threefry2x32(0u, 42u, 0u, 0u, A0, A1);
    threefry2x32(0u, 42u, 0u, 1u, B0, B1);

    // fork-join: ln_gemm (independent of CSR build) runs on a side stream.
    // Streams/events are created per call and intentionally not destroyed
    // (destroying a forked stream during capture is illegal; ~3 calls total,
    // host-side only).
    cudaStream_t s1;
    cudaEvent_t evFork, evLn;
    cudaStreamCreateWithFlags(&s1, cudaStreamNonBlocking);
    cudaEventCreateWithFlags(&evFork, cudaEventDisableTiming);
    cudaEventCreateWithFlags(&evLn, cudaEventDisableTiming);

    cudaEventRecord(evFork, 0);
    cudaStreamWaitEvent(s1, evFork, 0);
    k_ln_gemm<<<592, 256, 0, s1>>>(x, gamma, beta, W1);
    cudaEventRecord(evLn, s1);

    k_hist<<<NE / 4 / 256, 256>>>(dst4);
    k_scan1<<<NB1, 256>>>();
    k_scan2<<<1, 512>>>();
    k_scan3<<<NB1, 256>>>();
    k_fill<<<NE / 4 / 256, 256>>>(src4, dst4);

    cudaStreamWaitEvent(0, evLn, 0);
    k_scale<<<3125, 256>>>();
    k_gather<<<12500, 256>>>(0);
    k_post1<<<TOT / 256, 256>>>(b1, W2, A0, A1);
    k_gather<<<12500, 256>>>(1);
    k_final<<<TOT / 256, 256>>>(out, b2, B0, B1);
}